// round 10
// baseline (speedup 1.0000x reference)
#include <cuda_runtime.h>
#include <cuda_fp16.h>
#include <math.h>
#include <stdint.h>

#define D 128
#define NE 8192
#define NT 8192
#define EPSF 1e-8f
#define RPB 16

#define KT 128              // fp16 K
#define LDS_STRIDE 136      // padded smem row stride (elements)

#define TILES_N 32          // 8192 / 256
#define NTILES 2048         // (8192/128) * (8192/256)
#define GEMM_GRID 148
#define A_BYTES (128 * LDS_STRIDE * 2)
#define STAGE_BYTES ((128 + 256) * LDS_STRIDE * 2)   // 104448
#define GEMM_SMEM (2 * STAGE_BYTES)                  // 208896

// ---------------------------------------------------------------------------
// Device globals (no allocation allowed)
// ---------------------------------------------------------------------------
__device__ float g_C[D * D];
__device__ float g_h1[NE];
__device__ float g_h2[NT];
__device__ __align__(16) __half g_Ae[NE * KT];
__device__ __align__(16) __half g_At[NT * KT];

// ---------------------------------------------------------------------------
__device__ __forceinline__ uint32_t smem_u32(const void* p) {
    uint32_t a;
    asm("{ .reg .u64 t; cvta.to.shared.u64 t, %1; cvt.u32.u64 %0, t; }"
        : "=r"(a) : "l"(p));
    return a;
}

__device__ __forceinline__ void cp_async16(uint32_t sdst, const void* gsrc) {
    asm volatile("cp.async.cg.shared.global [%0], [%1], 16;"
                 :: "r"(sdst), "l"(gsrc) : "memory");
}

#define CP_COMMIT() asm volatile("cp.async.commit_group;" ::: "memory")

__device__ __forceinline__ void ldsm_x4(uint32_t (&r)[4], uint32_t addr) {
    asm volatile("ldmatrix.sync.aligned.m8n8.x4.shared.b16 {%0,%1,%2,%3}, [%4];"
                 : "=r"(r[0]), "=r"(r[1]), "=r"(r[2]), "=r"(r[3]) : "r"(addr));
}

__device__ __forceinline__ void mma16816(float (&d)[4], const uint32_t (&a)[4],
                                         uint32_t b0, uint32_t b1) {
    asm volatile(
        "mma.sync.aligned.m16n8k16.row.col.f32.f16.f16.f32 "
        "{%0,%1,%2,%3}, {%4,%5,%6,%7}, {%8,%9}, {%0,%1,%2,%3};"
        : "+f"(d[0]), "+f"(d[1]), "+f"(d[2]), "+f"(d[3])
        : "r"(a[0]), "r"(a[1]), "r"(a[2]), "r"(a[3]), "r"(b0), "r"(b1));
}

// ---------------------------------------------------------------------------
// C = W @ U_k : 128 CTAs x 128 threads, one C row per CTA.
// ---------------------------------------------------------------------------
__global__ __launch_bounds__(128)
void build_C_kernel(const float* __restrict__ W,
                    const float* __restrict__ U) {
    __shared__ float Wrow[128];
    int d = blockIdx.x;
    int k = threadIdx.x;
    Wrow[k] = W[d * 128 + k];
    __syncthreads();

    float acc = 0.f;
#pragma unroll 16
    for (int i = 0; i < 128; i++)
        acc = fmaf(Wrow[i], U[i * 128 + k], acc);
    g_C[d * 128 + k] = acc;
}

// ---------------------------------------------------------------------------
// Merged projection: grid (NE/RPB, 2); y=0 enroll, y=1 test.
// ---------------------------------------------------------------------------
__global__ __launch_bounds__(256)
void project_kernel(const float* __restrict__ Xe,
                    const float* __restrict__ Xt,
                    const float* __restrict__ miu,
                    const float* __restrict__ Q,
                    const float* __restrict__ lam) {
    __shared__ __align__(16) float v[RPB][128];
    __shared__ __align__(16) float ys[RPB][128];
    __shared__ float red[RPB][4];

    int which = blockIdx.y;
    const float* X = which ? Xt : Xe;
    int t = threadIdx.x & 127;
    int rg = threadIdx.x >> 7;
    int r0 = rg * 8;
    int lane = threadIdx.x & 31;
    int w = (threadIdx.x >> 5) & 3;
    int n0 = blockIdx.x * RPB;
    float mu = miu[t];

    float xr[8];
#pragma unroll
    for (int i = 0; i < 8; i++)
        xr[i] = X[(size_t)(n0 + r0 + i) * D + t] - mu;

#pragma unroll
    for (int i = 0; i < 8; i++) {
        float s = xr[i] * xr[i];
#pragma unroll
        for (int o = 16; o > 0; o >>= 1) s += __shfl_xor_sync(0xffffffffu, s, o);
        if (lane == 0) red[r0 + i][w] = s;
    }
    __syncthreads();
#pragma unroll
    for (int i = 0; i < 8; i++) {
        float tot = red[r0 + i][0] + red[r0 + i][1] +
                    red[r0 + i][2] + red[r0 + i][3];
        v[r0 + i][t] = xr[i] / (sqrtf(tot) + EPSF);
    }
    __syncthreads();

    float acc[8];
#pragma unroll
    for (int i = 0; i < 8; i++) acc[i] = 0.f;
#pragma unroll 4
    for (int d = 0; d < D; d += 4) {
        float c0 = g_C[(d + 0) * D + t];
        float c1 = g_C[(d + 1) * D + t];
        float c2 = g_C[(d + 2) * D + t];
        float c3 = g_C[(d + 3) * D + t];
#pragma unroll
        for (int i = 0; i < 8; i++) {
            float4 vv = *(const float4*)&v[r0 + i][d];
            acc[i] = fmaf(c0, vv.x, acc[i]);
            acc[i] = fmaf(c1, vv.y, acc[i]);
            acc[i] = fmaf(c2, vv.z, acc[i]);
            acc[i] = fmaf(c3, vv.w, acc[i]);
        }
    }
#pragma unroll
    for (int i = 0; i < 8; i++) ys[r0 + i][t] = acc[i];
    __syncthreads();

    float qacc[8];
#pragma unroll
    for (int i = 0; i < 8; i++) qacc[i] = 0.f;
#pragma unroll 4
    for (int j = 0; j < D; j += 4) {
        float q0 = Q[(j + 0) * D + t];
        float q1 = Q[(j + 1) * D + t];
        float q2 = Q[(j + 2) * D + t];
        float q3 = Q[(j + 3) * D + t];
#pragma unroll
        for (int i = 0; i < 8; i++) {
            float4 yy = *(const float4*)&ys[r0 + i][j];
            qacc[i] = fmaf(q0, yy.x, qacc[i]);
            qacc[i] = fmaf(q1, yy.y, qacc[i]);
            qacc[i] = fmaf(q2, yy.z, qacc[i]);
            qacc[i] = fmaf(q3, yy.w, qacc[i]);
        }
    }
#pragma unroll
    for (int i = 0; i < 8; i++) {
        float p = acc[i] * qacc[i];
#pragma unroll
        for (int o = 16; o > 0; o >>= 1) p += __shfl_xor_sync(0xffffffffu, p, o);
        if (lane == 0) red[r0 + i][w] = p;
    }
    __syncthreads();
    if (t < 8) {
        int row = r0 + t;
        float h = red[row][0] + red[row][1] + red[row][2] + red[row][3];
        if (which == 0) g_h1[n0 + row] = h;
        else            g_h2[n0 + row] = h;
    }

    __half* dst = which ? g_At : g_Ae;
    float f = which ? 1.f : 2.f * lam[t];
#pragma unroll
    for (int i = 0; i < 8; i++) {
        float val = ys[r0 + i][t] * f;
        dst[(size_t)(n0 + r0 + i) * KT + t] = __float2half_rn(val);
    }
}

// ---------------------------------------------------------------------------
// Persistent HMMA GEMM: grid 148, 512 threads (16 warps, 2x8 of 64x32).
// Tile 128(M) x 256(N); smem double-buffered stages; cp.async prefetch of
// tile t+GRID overlaps the MMA phase of tile t.
// ---------------------------------------------------------------------------
__device__ __forceinline__ void load_tile(uint32_t sA, uint32_t sB,
                                          int t, int tid) {
    int bm0 = (t >> 5) * 128;        // t / TILES_N
    int bn0 = (t & 31) * 256;        // t % TILES_N
    const char* gA = (const char*)(g_Ae + (size_t)bm0 * KT);
    const char* gB = (const char*)(g_At + (size_t)bn0 * KT);
    // A: 128 rows x 16 chunks = 2048; B: 256 rows x 16 chunks = 4096
#pragma unroll
    for (int u = 0; u < 4; u++) {
        int c = u * 512 + tid;
        int row = c >> 4, cc = c & 15;
        cp_async16(sA + (uint32_t)(row * LDS_STRIDE * 2 + cc * 16),
                   gA + row * (KT * 2) + cc * 16);
    }
#pragma unroll
    for (int u = 0; u < 8; u++) {
        int c = u * 512 + tid;
        int row = c >> 4, cc = c & 15;
        cp_async16(sB + (uint32_t)(row * LDS_STRIDE * 2 + cc * 16),
                   gB + row * (KT * 2) + cc * 16);
    }
}

__global__ __launch_bounds__(512, 1)
void gemm_hmma(float* __restrict__ out) {
    extern __shared__ char sm[];
    uint32_t s0 = smem_u32(sm);

    int tid = threadIdx.x;
    int lane = tid & 31, wid = tid >> 5;

    int m0 = (wid >> 3) * 64;      // 2 m-groups
    int n0 = (wid & 7) * 32;       // 8 n-groups
    int rowA = lane & 15;
    int kselA = (lane >> 4) << 3;
    int nrow = ((lane >> 4) & 1) * 8 + (lane & 7);
    int kselB = ((lane >> 3) & 1) * 8;

    int t = blockIdx.x;
    if (t < NTILES)
        load_tile(s0, s0 + A_BYTES, t, tid);
    CP_COMMIT();
    int stage = 0;

    while (t < NTILES) {
        int tn = t + GEMM_GRID;
        uint32_t sN = s0 + (uint32_t)(stage ^ 1) * STAGE_BYTES;
        if (tn < NTILES)
            load_tile(sN, sN + A_BYTES, tn, tid);
        CP_COMMIT();
        asm volatile("cp.async.wait_group 1;" ::: "memory");
        __syncthreads();

        uint32_t sA = s0 + (uint32_t)stage * STAGE_BYTES;
        uint32_t sB = sA + A_BYTES;
        uint32_t adA[4];
#pragma unroll
        for (int mi = 0; mi < 4; mi++)
            adA[mi] = sA + (uint32_t)((m0 + mi * 16 + rowA) * LDS_STRIDE + kselA) * 2u;
        uint32_t adB[2];
#pragma unroll
        for (int j = 0; j < 2; j++)
            adB[j] = sB + (uint32_t)((n0 + j * 16 + nrow) * LDS_STRIDE + kselB) * 2u;

        float acc[4][4][4];
#pragma unroll
        for (int mi = 0; mi < 4; mi++)
#pragma unroll
            for (int nj = 0; nj < 4; nj++)
#pragma unroll
                for (int e = 0; e < 4; e++) acc[mi][nj][e] = 0.f;

#pragma unroll
        for (int k = 0; k < 8; k++) {
            uint32_t off = (uint32_t)k * 32u;
            uint32_t a[4][4];
#pragma unroll
            for (int mi = 0; mi < 4; mi++) ldsm_x4(a[mi], adA[mi] + off);
            uint32_t bfr[2][4];
#pragma unroll
            for (int j = 0; j < 2; j++) ldsm_x4(bfr[j], adB[j] + off);
#pragma unroll
            for (int mi = 0; mi < 4; mi++) {
#pragma unroll
                for (int j = 0; j < 2; j++) {
                    mma16816(acc[mi][2 * j],     a[mi], bfr[j][0], bfr[j][1]);
                    mma16816(acc[mi][2 * j + 1], a[mi], bfr[j][2], bfr[j][3]);
                }
            }
        }
        __syncthreads();   // all reads of this stage done before it is refilled

        // epilogue: + h1[row] + h2[col]
        int bm0 = (t >> 5) * 128;
        int bn0 = (t & 31) * 256;
        int r0base = bm0 + m0 + (lane >> 2);
        int cbase = bn0 + n0 + 2 * (lane & 3);

        float h2v[4][2];
#pragma unroll
        for (int nj = 0; nj < 4; nj++) {
            h2v[nj][0] = g_h2[cbase + nj * 8];
            h2v[nj][1] = g_h2[cbase + nj * 8 + 1];
        }

#pragma unroll
        for (int mi = 0; mi < 4; mi++) {
            int gr0 = r0base + mi * 16;
            int gr1 = gr0 + 8;
            float h10 = g_h1[gr0];
            float h11 = g_h1[gr1];
#pragma unroll
            for (int nj = 0; nj < 4; nj++) {
                int gc = cbase + nj * 8;
                float2 v0 = make_float2(acc[mi][nj][0] + h10 + h2v[nj][0],
                                        acc[mi][nj][1] + h10 + h2v[nj][1]);
                float2 v1 = make_float2(acc[mi][nj][2] + h11 + h2v[nj][0],
                                        acc[mi][nj][3] + h11 + h2v[nj][1]);
                *(float2*)(out + (size_t)gr0 * NT + gc) = v0;
                *(float2*)(out + (size_t)gr1 * NT + gc) = v1;
            }
        }

        stage ^= 1;
        t = tn;
    }
}

// ---------------------------------------------------------------------------
extern "C" void kernel_launch(void* const* d_in, const int* in_sizes, int n_in,
                              void* d_out, int out_size) {
    const float* x_enroll = (const float*)d_in[0];
    const float* x_test   = (const float*)d_in[1];
    const float* W        = (const float*)d_in[2];
    const float* miu      = (const float*)d_in[3];
    const float* lam      = (const float*)d_in[4];
    const float* U_k      = (const float*)d_in[5];
    const float* Q_hat    = (const float*)d_in[6];
    float* out = (float*)d_out;

    build_C_kernel<<<128, 128>>>(W, U_k);
    project_kernel<<<dim3(NE / RPB, 2), 256>>>(x_enroll, x_test, miu, Q_hat, lam);

    cudaFuncSetAttribute(gemm_hmma, cudaFuncAttributeMaxDynamicSharedMemorySize,
                         GEMM_SMEM);
    gemm_hmma<<<GEMM_GRID, 512, GEMM_SMEM>>>(out);
}

// round 12
// speedup vs baseline: 1.4167x; 1.4167x over previous
#include <cuda_runtime.h>
#include <cuda_fp16.h>
#include <math.h>
#include <stdint.h>

#define D 128
#define NE 8192
#define NT 8192
#define EPSF 1e-8f

#define KT 128              // fp16 K
#define LDS_STRIDE 136      // padded smem row stride (elements)
#define BUF_BYTES (128 * LDS_STRIDE * 2)   // 34816 per fp16 buffer

// ---------------------------------------------------------------------------
// Device globals (no allocation allowed)
// ---------------------------------------------------------------------------
__device__ float g_h1[NE];
__device__ float g_h2[NT];
__device__ __align__(16) __half g_Ae[NE * KT];
__device__ __align__(16) __half g_At[NT * KT];
// C^T = (W@U_k)^T as fp16 hi/lo, layout [k][d]
__device__ __align__(16) __half g_CtrHi[D * D];
__device__ __align__(16) __half g_CtrLo[D * D];
// Q_hat as fp16 hi/lo, row-major (symmetric -> usable as col-major B)
__device__ __align__(16) __half g_QHi[D * D];
__device__ __align__(16) __half g_QLo[D * D];

// ---------------------------------------------------------------------------
__device__ __forceinline__ uint32_t smem_u32(const void* p) {
    uint32_t a;
    asm("{ .reg .u64 t; cvta.to.shared.u64 t, %1; cvt.u32.u64 %0, t; }"
        : "=r"(a) : "l"(p));
    return a;
}

__device__ __forceinline__ void cp_async16(uint32_t sdst, const void* gsrc) {
    asm volatile("cp.async.cg.shared.global [%0], [%1], 16;"
                 :: "r"(sdst), "l"(gsrc) : "memory");
}

#define CP_COMMIT() asm volatile("cp.async.commit_group;" ::: "memory")
#define CP_WAIT0()  asm volatile("cp.async.wait_group 0;" ::: "memory")

__device__ __forceinline__ void ldsm_x4(uint32_t (&r)[4], uint32_t addr) {
    asm volatile("ldmatrix.sync.aligned.m8n8.x4.shared.b16 {%0,%1,%2,%3}, [%4];"
                 : "=r"(r[0]), "=r"(r[1]), "=r"(r[2]), "=r"(r[3]) : "r"(addr));
}

__device__ __forceinline__ void mma16816(float (&d)[4], const uint32_t (&a)[4],
                                         uint32_t b0, uint32_t b1) {
    asm volatile(
        "mma.sync.aligned.m16n8k16.row.col.f32.f16.f16.f32 "
        "{%0,%1,%2,%3}, {%4,%5,%6,%7}, {%8,%9}, {%0,%1,%2,%3};"
        : "+f"(d[0]), "+f"(d[1]), "+f"(d[2]), "+f"(d[3])
        : "r"(a[0]), "r"(a[1]), "r"(a[2]), "r"(a[3]), "r"(b0), "r"(b1));
}

// ---------------------------------------------------------------------------
// build_C: C[d][k] = sum_i W[d][i]U[i][k]; emit Ctr (hi/lo, [k][d]) and
// Q_hat hi/lo (row-major copy). grid 128 (d), 128 threads (k).
// ---------------------------------------------------------------------------
__global__ __launch_bounds__(128)
void build_C_kernel(const float* __restrict__ W,
                    const float* __restrict__ U,
                    const float* __restrict__ Q) {
    __shared__ float Wrow[128];
    int d = blockIdx.x;
    int k = threadIdx.x;
    Wrow[k] = W[d * 128 + k];
    __syncthreads();

    float acc = 0.f;
#pragma unroll 16
    for (int i = 0; i < 128; i++)
        acc = fmaf(Wrow[i], U[i * 128 + k], acc);

    __half chi = __float2half_rn(acc);
    __half clo = __float2half_rn(acc - __half2float(chi));
    g_CtrHi[k * 128 + d] = chi;     // transposed store: [k][d]
    g_CtrLo[k * 128 + d] = clo;

    float q = Q[d * 128 + k];
    __half qhi = __float2half_rn(q);
    __half qlo = __float2half_rn(q - __half2float(qhi));
    g_QHi[d * 128 + k] = qhi;
    g_QLo[d * 128 + k] = qlo;
}

// ---------------------------------------------------------------------------
// project_tc: one CTA per 128 rows. grid (64, 2): y=0 enroll, y=1 test.
// 256 threads, 8 warps (2 m-groups x 4 n-groups, warp tile 64x32).
//   normalize -> v hi/lo ; Y = V*C (3-term) ; pack Ae/At ; Z = Y*Q (3-term) ;
//   h = sum(Y .* Z) from live fragments.
// ---------------------------------------------------------------------------
#define SM_VHI 0
#define SM_VLO (SM_VHI + BUF_BYTES)
#define SM_BHI (SM_VLO + BUF_BYTES)
#define SM_BLO (SM_BHI + BUF_BYTES)
#define SM_YHI (SM_BLO + BUF_BYTES)
#define SM_YLO (SM_YHI + BUF_BYTES)
#define SM_LAM (SM_YLO + BUF_BYTES)        // 512 B
#define SM_HSUM (SM_LAM + 512)             // 512 B
#define SM_RED (SM_HSUM + 512)             // 512 B
#define PROJ_SMEM (SM_RED + 512)

__global__ __launch_bounds__(256)
void project_tc(const float* __restrict__ Xe,
                const float* __restrict__ Xt,
                const float* __restrict__ miu,
                const float* __restrict__ lam) {
    extern __shared__ char sm[];
    uint32_t sb = smem_u32(sm);
    __half* vhi_s = (__half*)(sm + SM_VHI);
    __half* vlo_s = (__half*)(sm + SM_VLO);
    float* lam_s = (float*)(sm + SM_LAM);
    float* hsum = (float*)(sm + SM_HSUM);
    float* red = (float*)(sm + SM_RED);

    int tid = threadIdx.x;
    int lane = tid & 31, wid = tid >> 5;
    int which = blockIdx.y;
    int n0g = blockIdx.x * 128;
    const float* X = which ? Xt : Xe;

    // start Ctr loads (B operand of gemm1): 128 rows x 256 B = 2048 chunks
#pragma unroll
    for (int u = 0; u < 8; u++) {
        int c = u * 256 + tid;               // 0..2047
        int row = c >> 4, cc = c & 15;       // 16 x 16B = 256 B per row
        cp_async16(sb + SM_BHI + (uint32_t)(row * LDS_STRIDE * 2 + cc * 16),
                   (const char*)g_CtrHi + row * 256 + cc * 16);
        cp_async16(sb + SM_BLO + (uint32_t)(row * LDS_STRIDE * 2 + cc * 16),
                   (const char*)g_CtrLo + row * 256 + cc * 16);
    }
    CP_COMMIT();

    if (tid < 128) { lam_s[tid] = lam[tid]; hsum[tid] = 0.f; }

    // ---- phase A: normalize, split v into hi/lo smem ----
    int t = tid & 127;
    int rg = tid >> 7;                 // 0/1 -> rows [rg*64, rg*64+64)
    int w4 = (tid >> 5) & 3;
    float mu = miu[t];

#pragma unroll
    for (int ch = 0; ch < 4; ch++) {
        int rbase = rg * 64 + ch * 16;
        float xv[16];
#pragma unroll
        for (int i = 0; i < 16; i++)
            xv[i] = X[(size_t)(n0g + rbase + i) * D + t] - mu;
#pragma unroll
        for (int i = 0; i < 16; i++) {
            float s = xv[i] * xv[i];
#pragma unroll
            for (int o = 16; o > 0; o >>= 1)
                s += __shfl_xor_sync(0xffffffffu, s, o);
            if (lane == 0) red[rg * 64 + i * 4 + w4] = s;
        }
        __syncthreads();
#pragma unroll
        for (int i = 0; i < 16; i++) {
            int base = rg * 64 + i * 4;
            float tot = red[base] + red[base + 1] + red[base + 2] + red[base + 3];
            float vv = xv[i] / (sqrtf(tot) + EPSF);
            __half hi = __float2half_rn(vv);
            __half lo = __float2half_rn(vv - __half2float(hi));
            vhi_s[(rbase + i) * LDS_STRIDE + t] = hi;
            vlo_s[(rbase + i) * LDS_STRIDE + t] = lo;
        }
        __syncthreads();
    }

    CP_WAIT0();
    __syncthreads();

    int m0 = (wid >> 2) * 64;
    int n0 = (wid & 3) * 32;
    int rowA = lane & 15;
    int kselA = (lane >> 4) << 3;
    int nrow = ((lane >> 4) & 1) * 8 + (lane & 7);
    int kselB = ((lane >> 3) & 1) * 8;

    // ---- gemm1: Y = V * C, 3-term hi/lo ----
    float accY[4][4][4];
#pragma unroll
    for (int mi = 0; mi < 4; mi++)
#pragma unroll
        for (int nj = 0; nj < 4; nj++)
#pragma unroll
            for (int e = 0; e < 4; e++) accY[mi][nj][e] = 0.f;

#pragma unroll
    for (int term = 0; term < 3; term++) {
        uint32_t aB = sb + ((term == 2) ? SM_VLO : SM_VHI);
        uint32_t bB = sb + ((term == 1) ? SM_BLO : SM_BHI);
        uint32_t adA[4];
#pragma unroll
        for (int mi = 0; mi < 4; mi++)
            adA[mi] = aB + (uint32_t)((m0 + mi * 16 + rowA) * LDS_STRIDE + kselA) * 2u;
        uint32_t adB[2];
#pragma unroll
        for (int j = 0; j < 2; j++)
            adB[j] = bB + (uint32_t)((n0 + j * 16 + nrow) * LDS_STRIDE + kselB) * 2u;
#pragma unroll
        for (int k = 0; k < 8; k++) {
            uint32_t off = (uint32_t)k * 32u;
            uint32_t a[4][4];
#pragma unroll
            for (int mi = 0; mi < 4; mi++) ldsm_x4(a[mi], adA[mi] + off);
            uint32_t bfr[2][4];
#pragma unroll
            for (int j = 0; j < 2; j++) ldsm_x4(bfr[j], adB[j] + off);
#pragma unroll
            for (int mi = 0; mi < 4; mi++)
#pragma unroll
                for (int j = 0; j < 2; j++) {
                    mma16816(accY[mi][2 * j],     a[mi], bfr[j][0], bfr[j][1]);
                    mma16816(accY[mi][2 * j + 1], a[mi], bfr[j][2], bfr[j][3]);
                }
        }
    }
    __syncthreads();   // done reading Ctr from BHI/BLO

    // start Q loads into B buffers: 128 rows x 256 B
#pragma unroll
    for (int u = 0; u < 8; u++) {
        int c = u * 256 + tid;
        int row = c >> 4, cc = c & 15;
        cp_async16(sb + SM_BHI + (uint32_t)(row * LDS_STRIDE * 2 + cc * 16),
                   (const char*)g_QHi + row * 256 + cc * 16);
        cp_async16(sb + SM_BLO + (uint32_t)(row * LDS_STRIDE * 2 + cc * 16),
                   (const char*)g_QLo + row * 256 + cc * 16);
    }
    CP_COMMIT();

    // write Y (hi/lo) to smem and pack outputs to global
    __half* yhi_s = (__half*)(sm + SM_YHI);
    __half* ylo_s = (__half*)(sm + SM_YLO);
    __half* dst = which ? g_At : g_Ae;

#pragma unroll
    for (int mi = 0; mi < 4; mi++) {
        int r0 = m0 + mi * 16 + (lane >> 2);
        int r1 = r0 + 8;
#pragma unroll
        for (int nj = 0; nj < 4; nj++) {
            int c = n0 + nj * 8 + 2 * (lane & 3);
            float y00 = accY[mi][nj][0], y01 = accY[mi][nj][1];
            float y10 = accY[mi][nj][2], y11 = accY[mi][nj][3];

            __half h00 = __float2half_rn(y00), h01 = __float2half_rn(y01);
            __half h10 = __float2half_rn(y10), h11 = __float2half_rn(y11);
            *(__half2*)&yhi_s[r0 * LDS_STRIDE + c] = __halves2half2(h00, h01);
            *(__half2*)&yhi_s[r1 * LDS_STRIDE + c] = __halves2half2(h10, h11);
            *(__half2*)&ylo_s[r0 * LDS_STRIDE + c] =
                __halves2half2(__float2half_rn(y00 - __half2float(h00)),
                               __float2half_rn(y01 - __half2float(h01)));
            *(__half2*)&ylo_s[r1 * LDS_STRIDE + c] =
                __halves2half2(__float2half_rn(y10 - __half2float(h10)),
                               __float2half_rn(y11 - __half2float(h11)));

            float f0 = which ? 1.f : 2.f * lam_s[c];
            float f1 = which ? 1.f : 2.f * lam_s[c + 1];
            *(__half2*)&dst[(size_t)(n0g + r0) * KT + c] =
                __halves2half2(__float2half_rn(y00 * f0), __float2half_rn(y01 * f1));
            *(__half2*)&dst[(size_t)(n0g + r1) * KT + c] =
                __halves2half2(__float2half_rn(y10 * f0), __float2half_rn(y11 * f1));
        }
    }

    CP_WAIT0();
    __syncthreads();   // Y smem visible, Q loaded

    // ---- gemm2: Z = Y * Q, 3-term hi/lo ----
    float accZ[4][4][4];
#pragma unroll
    for (int mi = 0; mi < 4; mi++)
#pragma unroll
        for (int nj = 0; nj < 4; nj++)
#pragma unroll
            for (int e = 0; e < 4; e++) accZ[mi][nj][e] = 0.f;

#pragma unroll
    for (int term = 0; term < 3; term++) {
        uint32_t aB = sb + ((term == 2) ? SM_YLO : SM_YHI);
        uint32_t bB = sb + ((term == 1) ? SM_BLO : SM_BHI);
        uint32_t adA[4];
#pragma unroll
        for (int mi = 0; mi < 4; mi++)
            adA[mi] = aB + (uint32_t)((m0 + mi * 16 + rowA) * LDS_STRIDE + kselA) * 2u;
        uint32_t adB[2];
#pragma unroll
        for (int j = 0; j < 2; j++)
            adB[j] = bB + (uint32_t)((n0 + j * 16 + nrow) * LDS_STRIDE + kselB) * 2u;
#pragma unroll
        for (int k = 0; k < 8; k++) {
            uint32_t off = (uint32_t)k * 32u;
            uint32_t a[4][4];
#pragma unroll
            for (int mi = 0; mi < 4; mi++) ldsm_x4(a[mi], adA[mi] + off);
            uint32_t bfr[2][4];
#pragma unroll
            for (int j = 0; j < 2; j++) ldsm_x4(bfr[j], adB[j] + off);
#pragma unroll
            for (int mi = 0; mi < 4; mi++)
#pragma unroll
                for (int j = 0; j < 2; j++) {
                    mma16816(accZ[mi][2 * j],     a[mi], bfr[j][0], bfr[j][1]);
                    mma16816(accZ[mi][2 * j + 1], a[mi], bfr[j][2], bfr[j][3]);
                }
        }
    }

    // ---- h = sum_k Y[r][k] * Z[r][k] ----
#pragma unroll
    for (int mi = 0; mi < 4; mi++) {
        float p0 = 0.f, p1 = 0.f;
#pragma unroll
        for (int nj = 0; nj < 4; nj++) {
            p0 += accY[mi][nj][0] * accZ[mi][nj][0] +
                  accY[mi][nj][1] * accZ[mi][nj][1];
            p1 += accY[mi][nj][2] * accZ[mi][nj][2] +
                  accY[mi][nj][3] * accZ[mi][nj][3];
        }
        p0 += __shfl_xor_sync(0xffffffffu, p0, 1);
        p0 += __shfl_xor_sync(0xffffffffu, p0, 2);
        p1 += __shfl_xor_sync(0xffffffffu, p1, 1);
        p1 += __shfl_xor_sync(0xffffffffu, p1, 2);
        if ((lane & 3) == 0) {
            int r0 = m0 + mi * 16 + (lane >> 2);
            atomicAdd(&hsum[r0], p0);
            atomicAdd(&hsum[r0 + 8], p1);
        }
    }
    __syncthreads();

    if (tid < 128) {
        if (which == 0) g_h1[n0g + tid] = hsum[tid];
        else            g_h2[n0g + tid] = hsum[tid];
    }
}

// ---------------------------------------------------------------------------
// HMMA GEMM (round-9 proven): 128x128 tile, 256 threads, 2 CTAs/SM.
// ---------------------------------------------------------------------------
#define GEMM_SMEM (2 * 128 * LDS_STRIDE * 2)   // 69632

__global__ __launch_bounds__(256, 2)
void gemm_hmma(float* __restrict__ out) {
    extern __shared__ char sm[];
    uint32_t sA = smem_u32(sm);
    uint32_t sB = sA + 128 * LDS_STRIDE * 2;

    int tid = threadIdx.x;
    int lane = tid & 31, wid = tid >> 5;
    int bm0 = blockIdx.y * 128;
    int bn0 = blockIdx.x * 128;

    const char* gA = (const char*)(g_Ae + (size_t)bm0 * KT);
    const char* gB = (const char*)(g_At + (size_t)bn0 * KT);

#pragma unroll
    for (int u = 0; u < 16; u++) {
        int c = u * 256 + tid;           // 0..4095
        int tile = c >> 11;
        int row = (c >> 4) & 127;
        int cc = c & 15;
        const char* gsrc = (tile ? gB : gA) + row * (KT * 2) + cc * 16;
        uint32_t sdst = (tile ? sB : sA) +
                        (uint32_t)(row * LDS_STRIDE * 2 + cc * 16);
        cp_async16(sdst, gsrc);
    }
    CP_COMMIT();

    int m0 = (wid >> 2) * 64;
    int n0 = (wid & 3) * 32;
    int rowA = lane & 15;
    int kselA = (lane >> 4) << 3;
    uint32_t adA[4];
#pragma unroll
    for (int mi = 0; mi < 4; mi++)
        adA[mi] = sA + (uint32_t)((m0 + mi * 16 + rowA) * LDS_STRIDE + kselA) * 2u;
    int nrow = ((lane >> 4) & 1) * 8 + (lane & 7);
    int kselB = ((lane >> 3) & 1) * 8;
    uint32_t adB[2];
#pragma unroll
    for (int j = 0; j < 2; j++)
        adB[j] = sB + (uint32_t)((n0 + j * 16 + nrow) * LDS_STRIDE + kselB) * 2u;

    float acc[4][4][4];
#pragma unroll
    for (int mi = 0; mi < 4; mi++)
#pragma unroll
        for (int nj = 0; nj < 4; nj++)
#pragma unroll
            for (int e = 0; e < 4; e++) acc[mi][nj][e] = 0.f;

    CP_WAIT0();
    __syncthreads();

    uint32_t a[2][4][4];
    uint32_t bb[2][2][4];
#pragma unroll
    for (int mi = 0; mi < 4; mi++) ldsm_x4(a[0][mi], adA[mi]);
#pragma unroll
    for (int j = 0; j < 2; j++) ldsm_x4(bb[0][j], adB[j]);

#pragma unroll
    for (int k = 0; k < 8; k++) {
        int cur = k & 1, nxt = cur ^ 1;
        if (k < 7) {
            uint32_t off = (uint32_t)(k + 1) * 32u;
#pragma unroll
            for (int mi = 0; mi < 4; mi++) ldsm_x4(a[nxt][mi], adA[mi] + off);
#pragma unroll
            for (int j = 0; j < 2; j++) ldsm_x4(bb[nxt][j], adB[j] + off);
        }
#pragma unroll
        for (int mi = 0; mi < 4; mi++)
#pragma unroll
            for (int j = 0; j < 2; j++) {
                mma16816(acc[mi][2 * j],     a[cur][mi], bb[cur][j][0], bb[cur][j][1]);
                mma16816(acc[mi][2 * j + 1], a[cur][mi], bb[cur][j][2], bb[cur][j][3]);
            }
    }

    int r0base = bm0 + m0 + (lane >> 2);
    int cbase = bn0 + n0 + 2 * (lane & 3);

    float h2v[4][2];
#pragma unroll
    for (int nj = 0; nj < 4; nj++) {
        h2v[nj][0] = g_h2[cbase + nj * 8];
        h2v[nj][1] = g_h2[cbase + nj * 8 + 1];
    }

#pragma unroll
    for (int mi = 0; mi < 4; mi++) {
        int gr0 = r0base + mi * 16;
        int gr1 = gr0 + 8;
        float h10 = g_h1[gr0];
        float h11 = g_h1[gr1];
#pragma unroll
        for (int nj = 0; nj < 4; nj++) {
            int gc = cbase + nj * 8;
            float2 v0 = make_float2(acc[mi][nj][0] + h10 + h2v[nj][0],
                                    acc[mi][nj][1] + h10 + h2v[nj][1]);
            float2 v1 = make_float2(acc[mi][nj][2] + h11 + h2v[nj][0],
                                    acc[mi][nj][3] + h11 + h2v[nj][1]);
            *(float2*)(out + (size_t)gr0 * NT + gc) = v0;
            *(float2*)(out + (size_t)gr1 * NT + gc) = v1;
        }
    }
}

// ---------------------------------------------------------------------------
extern "C" void kernel_launch(void* const* d_in, const int* in_sizes, int n_in,
                              void* d_out, int out_size) {
    const float* x_enroll = (const float*)d_in[0];
    const float* x_test   = (const float*)d_in[1];
    const float* W        = (const float*)d_in[2];
    const float* miu      = (const float*)d_in[3];
    const float* lam      = (const float*)d_in[4];
    const float* U_k      = (const float*)d_in[5];
    const float* Q_hat    = (const float*)d_in[6];
    float* out = (float*)d_out;

    build_C_kernel<<<128, 128>>>(W, U_k, Q_hat);

    cudaFuncSetAttribute(project_tc, cudaFuncAttributeMaxDynamicSharedMemorySize,
                         PROJ_SMEM);
    project_tc<<<dim3(64, 2), 256, PROJ_SMEM>>>(x_enroll, x_test, miu, lam);

    cudaFuncSetAttribute(gemm_hmma, cudaFuncAttributeMaxDynamicSharedMemorySize,
                         GEMM_SMEM);
    dim3 grid(NT / 128, NE / 128);
    gemm_hmma<<<grid, 256, GEMM_SMEM>>>(out);
}